// round 3
// baseline (speedup 1.0000x reference)
#include <cuda_runtime.h>

// Depthwise 3x3 lateral conv (center tap excluded) + residual, NHWC f32.
// x: [32,56,56,256], kernel: [3,3,256], out: [32,56,56,256]
//
// Register-tiled HR=2 x WR=4 per thread (thread owns 4 channels via float4).
// R3 change: kernel taps moved from registers to shared memory (9 KB,
// conflict-free by lane->bank mapping), center tap staged as 1.0 so the
// residual add folds into the conv. __launch_bounds__(128,6) caps regs to
// lift occupancy from 16 to ~24 warps/SM (R2 was latency-bound at occ=22%).

#define H 56
#define W 56
#define C 256
#define C4 (C / 4)   // 64
#define HR 2
#define WR 4

__global__ __launch_bounds__(128, 6) void contour_kernel(
    const float* __restrict__ x,
    const float* __restrict__ kern,
    float* __restrict__ out)
{
    __shared__ float4 sk[9 * C4];   // [tap][c4], 9 KB

    const int tid = threadIdx.y * blockDim.x + threadIdx.x;  // 0..127
    const float4* __restrict__ k4 = reinterpret_cast<const float4*>(kern);
    for (int i = tid; i < 9 * C4; i += 128) {
        const int tap = i / C4;
        sk[i] = (tap == 4) ? make_float4(1.f, 1.f, 1.f, 1.f)  // residual fold
                           : k4[i];
    }
    __syncthreads();

    const int c4 = threadIdx.x;                          // 0..63
    const int wb = blockIdx.x * 8 + threadIdx.y * 4;     // 0,4,...,52
    const int hb = blockIdx.y * HR;                      // 0,2,...,54
    const int b  = blockIdx.z;

    const float4* __restrict__ xin = reinterpret_cast<const float4*>(x);
    float4* __restrict__ o = reinterpret_cast<float4*>(out);

    const size_t img = (size_t)b * H * W * C4;

    float4 acc[HR][WR];
    #pragma unroll
    for (int r = 0; r < HR; r++)
        #pragma unroll
        for (int j = 0; j < WR; j++)
            acc[r][j] = make_float4(0.f, 0.f, 0.f, 0.f);

    #pragma unroll
    for (int ih = 0; ih < HR + 2; ih++) {
        const int row = hb - 1 + ih;
        if (row < 0 || row >= H) continue;
        const size_t rb = img + (size_t)row * W * C4 + c4;

        // 6 consecutive-w float4 loads for this input row (OOB -> 0)
        float4 v[WR + 2];
        #pragma unroll
        for (int j = 0; j < WR + 2; j++) {
            const int col = wb - 1 + j;
            v[j] = (col >= 0 && col < W) ? xin[rb + (size_t)col * C4]
                                         : make_float4(0.f, 0.f, 0.f, 0.f);
        }

        #pragma unroll
        for (int r = 0; r < HR; r++) {
            const int kh = ih - r;          // kernel row fed by this input row
            if (kh < 0 || kh > 2) continue;
            #pragma unroll
            for (int dw = 0; dw < 3; dw++) {
                const float4 kk = sk[(kh * 3 + dw) * C4 + c4];
                #pragma unroll
                for (int j = 0; j < WR; j++) {
                    const float4 vv = v[j + dw];
                    acc[r][j].x = fmaf(vv.x, kk.x, acc[r][j].x);
                    acc[r][j].y = fmaf(vv.y, kk.y, acc[r][j].y);
                    acc[r][j].z = fmaf(vv.z, kk.z, acc[r][j].z);
                    acc[r][j].w = fmaf(vv.w, kk.w, acc[r][j].w);
                }
            }
        }
    }

    #pragma unroll
    for (int r = 0; r < HR; r++) {
        const size_t rb = img + (size_t)(hb + r) * W * C4 + c4;
        #pragma unroll
        for (int j = 0; j < WR; j++)
            o[rb + (size_t)(wb + j) * C4] = acc[r][j];
    }
}

extern "C" void kernel_launch(void* const* d_in, const int* in_sizes, int n_in,
                              void* d_out, int out_size)
{
    const float* x    = (const float*)d_in[0];   // [32,56,56,256]
    const float* kern = (const float*)d_in[1];   // [3,3,256]
    float* out        = (float*)d_out;

    dim3 block(C4, 2, 1);          // 128 threads; block covers 8 w, 2 h
    dim3 grid(W / 8, H / HR, 32);  // 7 x 28 x 32 = 6272 blocks
    contour_kernel<<<grid, block>>>(x, kern, out);
}

// round 4
// speedup vs baseline: 1.1599x; 1.1599x over previous
#include <cuda_runtime.h>

// Depthwise 3x3 lateral conv (center tap excluded) + residual, NHWC f32.
// x: [32,56,56,256], kernel: [3,3,256], out: [32,56,56,256]
//
// R4: float2 channel granularity (thread owns 2 channels), HR=2 x WR=4 spatial
// tile per thread. Taps live in registers (8 taps; residual folded as a direct
// add of the center pixel). ~halves register pressure vs the float4 version
// to lift occupancy (R2 was latency-bound at occ=22%) while keeping memory
// traffic per byte identical (3 loads/output, 256B contiguous per warp-load).

#define H 56
#define W 56
#define C 256
#define C2 (C / 2)   // 128
#define HR 2
#define WR 4

__device__ __forceinline__ float2 f2fma(float2 v, float2 k, float2 a) {
    a.x = fmaf(v.x, k.x, a.x);
    a.y = fmaf(v.y, k.y, a.y);
    return a;
}

__global__ __launch_bounds__(128, 6) void contour_kernel(
    const float* __restrict__ x,
    const float* __restrict__ kern,
    float* __restrict__ out)
{
    const int c2 = threadIdx.x;              // 0..127 (2 channels each)
    const int wb = blockIdx.x * WR;          // 0,4,...,52
    const int hb = blockIdx.y * HR;          // 0,2,...,54
    const int b  = blockIdx.z;

    const float2* __restrict__ xin = reinterpret_cast<const float2*>(x);
    const float2* __restrict__ k2  = reinterpret_cast<const float2*>(kern);
    float2* __restrict__ o = reinterpret_cast<float2*>(out);

    // 8 lateral taps -> registers (center tap handled separately as residual)
    float2 kreg[8];
    {
        int t = 0;
        #pragma unroll
        for (int tap = 0; tap < 9; tap++) {
            if (tap == 4) continue;
            kreg[t++] = k2[tap * C2 + c2];
        }
    }

    const size_t img = (size_t)b * H * W * C2;

    float2 acc[HR][WR];
    #pragma unroll
    for (int r = 0; r < HR; r++)
        #pragma unroll
        for (int j = 0; j < WR; j++)
            acc[r][j] = make_float2(0.f, 0.f);

    #pragma unroll
    for (int ih = 0; ih < HR + 2; ih++) {
        const int row = hb - 1 + ih;
        if (row < 0 || row >= H) continue;
        const size_t rb = img + (size_t)row * W * C2 + c2;

        // 6 consecutive-w float2 loads for this input row (OOB -> 0)
        float2 v[WR + 2];
        #pragma unroll
        for (int j = 0; j < WR + 2; j++) {
            const int col = wb - 1 + j;
            v[j] = (col >= 0 && col < W) ? xin[rb + (size_t)col * C2]
                                         : make_float2(0.f, 0.f);
        }

        #pragma unroll
        for (int r = 0; r < HR; r++) {
            const int kh = ih - r;          // kernel row fed by this input row
            if (kh < 0 || kh > 2) continue;
            #pragma unroll
            for (int dw = 0; dw < 3; dw++) {
                const bool is_center = (kh == 1 && dw == 1);
                // lateral tap index skipping the center slot
                const int lin = kh * 3 + dw;
                const int t = lin - (lin > 4 ? 1 : 0);
                #pragma unroll
                for (int j = 0; j < WR; j++) {
                    if (is_center) {
                        // residual: out += x at center pixel
                        acc[r][j].x += v[j + 1].x;
                        acc[r][j].y += v[j + 1].y;
                    } else {
                        acc[r][j] = f2fma(v[j + dw], kreg[t], acc[r][j]);
                    }
                }
            }
        }
    }

    #pragma unroll
    for (int r = 0; r < HR; r++) {
        const size_t rb = img + (size_t)(hb + r) * W * C2 + c2;
        #pragma unroll
        for (int j = 0; j < WR; j++)
            o[rb + (size_t)(wb + j) * C2] = acc[r][j];
    }
}

extern "C" void kernel_launch(void* const* d_in, const int* in_sizes, int n_in,
                              void* d_out, int out_size)
{
    const float* x    = (const float*)d_in[0];   // [32,56,56,256]
    const float* kern = (const float*)d_in[1];   // [3,3,256]
    float* out        = (float*)d_out;

    dim3 block(C2, 1, 1);            // 128 threads: all 256 channels as float2
    dim3 grid(W / WR, H / HR, 32);   // 14 x 28 x 32 = 12544 blocks
    contour_kernel<<<grid, block>>>(x, kern, out);
}

// round 5
// speedup vs baseline: 1.3179x; 1.1362x over previous
#include <cuda_runtime.h>

// Depthwise 3x3 lateral conv (center tap excluded) + residual, NHWC f32.
// x: [32,56,56,256], kernel: [3,3,256], out: [32,56,56,256]
//
// R5: block-uniform interior fast path. ~80% of blocks touch no image border;
// for those, all 24 input loads are issued branch-free off a single base
// pointer with immediate offsets (max MLP batching), no bounds ALU.
// Boundary blocks take the guarded path. float2 granularity, HR=2 x WR=4
// per thread, taps in registers, residual folded as center-pixel add.

#define H 56
#define W 56
#define C2 128        // channels as float2
#define HR 2
#define WR 4

__device__ __forceinline__ void f2fma(float2& a, float2 v, float2 k) {
    a.x = fmaf(v.x, k.x, a.x);
    a.y = fmaf(v.y, k.y, a.y);
}

__global__ __launch_bounds__(128, 8) void contour_kernel(
    const float* __restrict__ x,
    const float* __restrict__ kern,
    float* __restrict__ out)
{
    const int c2 = threadIdx.x;              // 0..127 (2 channels)
    const int wb = blockIdx.x * WR;          // 0,4,...,52
    const int hb = blockIdx.y * HR;          // 0,2,...,54
    const int b  = blockIdx.z;

    const float2* __restrict__ xin = reinterpret_cast<const float2*>(x);
    const float2* __restrict__ k2  = reinterpret_cast<const float2*>(kern);
    float2* __restrict__ o = reinterpret_cast<float2*>(out);

    // 8 lateral taps -> registers (center excluded; handled as residual add)
    float2 kreg[8];
    #pragma unroll
    for (int t = 0; t < 8; t++) {
        const int tap = t + (t >= 4 ? 1 : 0);
        kreg[t] = k2[tap * C2 + c2];
    }

    const int img = b * (H * W * C2);        // fits in int32 (12.8M max)

    float2 acc[HR][WR];
    #pragma unroll
    for (int r = 0; r < HR; r++)
        #pragma unroll
        for (int j = 0; j < WR; j++)
            acc[r][j] = make_float2(0.f, 0.f);

    const bool interior = (hb >= 1) & (hb + HR + 1 <= H) & (wb >= 1) & (wb + WR + 1 <= W);

    if (interior) {
        // base = (row hb-1, col wb-1); all loads base + compile-time offset
        const float2* __restrict__ p =
            xin + img + ((hb - 1) * W + (wb - 1)) * C2 + c2;

        #pragma unroll
        for (int ih = 0; ih < HR + 2; ih++) {
            float2 v[WR + 2];
            #pragma unroll
            for (int j = 0; j < WR + 2; j++)
                v[j] = p[(ih * W + j) * C2];

            #pragma unroll
            for (int r = 0; r < HR; r++) {
                const int kh = ih - r - (0);           // kernel row index
                if (kh < 0 || kh > 2) continue;
                #pragma unroll
                for (int dw = 0; dw < 3; dw++) {
                    const bool is_center = (kh == 1 && dw == 1);
                    const int lin = kh * 3 + dw;
                    const int t = lin - (lin > 4 ? 1 : 0);
                    #pragma unroll
                    for (int j = 0; j < WR; j++) {
                        if (is_center) {
                            acc[r][j].x += v[j + 1].x;  // residual
                            acc[r][j].y += v[j + 1].y;
                        } else {
                            f2fma(acc[r][j], v[j + dw], kreg[t]);
                        }
                    }
                }
            }
        }
    } else {
        #pragma unroll
        for (int ih = 0; ih < HR + 2; ih++) {
            const int row = hb - 1 + ih;
            if (row < 0 || row >= H) continue;
            const int rb = img + row * (W * C2) + c2;

            float2 v[WR + 2];
            #pragma unroll
            for (int j = 0; j < WR + 2; j++) {
                const int col = wb - 1 + j;
                v[j] = ((unsigned)col < (unsigned)W) ? xin[rb + col * C2]
                                                     : make_float2(0.f, 0.f);
            }

            #pragma unroll
            for (int r = 0; r < HR; r++) {
                const int kh = ih - r;
                if (kh < 0 || kh > 2) continue;
                #pragma unroll
                for (int dw = 0; dw < 3; dw++) {
                    const bool is_center = (kh == 1 && dw == 1);
                    const int lin = kh * 3 + dw;
                    const int t = lin - (lin > 4 ? 1 : 0);
                    #pragma unroll
                    for (int j = 0; j < WR; j++) {
                        if (is_center) {
                            acc[r][j].x += v[j + 1].x;
                            acc[r][j].y += v[j + 1].y;
                        } else {
                            f2fma(acc[r][j], v[j + dw], kreg[t]);
                        }
                    }
                }
            }
        }
    }

    #pragma unroll
    for (int r = 0; r < HR; r++) {
        const int rb = img + (hb + r) * (W * C2) + c2;
        #pragma unroll
        for (int j = 0; j < WR; j++)
            o[rb + (wb + j) * C2] = acc[r][j];
    }
}

extern "C" void kernel_launch(void* const* d_in, const int* in_sizes, int n_in,
                              void* d_out, int out_size)
{
    const float* x    = (const float*)d_in[0];   // [32,56,56,256]
    const float* kern = (const float*)d_in[1];   // [3,3,256]
    float* out        = (float*)d_out;

    dim3 block(C2, 1, 1);            // 128 threads
    dim3 grid(W / WR, H / HR, 32);   // 14 x 28 x 32 = 12544 blocks
    contour_kernel<<<grid, block>>>(x, kern, out);
}